// round 13
// baseline (speedup 1.0000x reference)
#include <cuda_runtime.h>
#include <cuda_fp16.h>
#include <cstdint>

// CMPModel density matrix via fp16 mma.sync m16n8k16 (f32 accum), sm_103.
// V=50000, D=256, S=128, B=64.
//
// R[k,d]=word_emb[q[k],d], I[k,d]=cmp_emb[q[k],d]*pos[k]
//   real[d,e] = sum_k w[k]( R[k,d]R[k,e] + I[k,d]I[k,e] )
//   imag[d,e] = sum_k w[k]( I[k,d]R[k,e] - R[k,d]I[k,e] )
//
// LSU-floor model: wall time == total-chip LDG x 1.82 cyc / 148 SMs.
// So: CTA = (batch, d-half) -> 128 CTAs; each gathers full 256-feat rows
// ONCE (unscaled R/I fp16 tiles; HALF the chip-total LDGs of the quadrant
// scheme), 4 pipelined chunk stages (32KB each, all resident), then:
//   pass et=0: chunked compute overlapped with gather of later chunks
//   pass et=1: pure MMA from resident smem - zero loads, zero barriers.
// B fragments get w on the fly via mul.f16x2 (validated R11/R12).
// Fragments via ldmatrix.x4.trans ([k][256feat], 512B rows, ^(k&7) swizzle).
// Imag minus sign: negate aR fragment (XOR 0x80008000).

#define D_DIM 256
#define S_LEN 128
#define B_DIM 64
#define KC    32

#define R_OFF 0
#define I_OFF 16384
#define STAGE_BYTES 32768                   // R(16KB) + I(16KB) per 32 tokens
#define SMEM_BYTES  (4 * STAGE_BYTES)       // 128KB: whole S resident

__device__ __forceinline__ void ldmx4t(uint32_t* r, uint32_t addr) {
    asm("ldmatrix.sync.aligned.m8n8.x4.trans.shared.b16 {%0,%1,%2,%3}, [%4];"
        : "=r"(r[0]), "=r"(r[1]), "=r"(r[2]), "=r"(r[3]) : "r"(addr));
}

__device__ __forceinline__ void mma16(float* c, const uint32_t* a,
                                      const uint32_t* b) {
    asm("mma.sync.aligned.m16n8k16.row.col.f32.f16.f16.f32 "
        "{%0,%1,%2,%3}, {%4,%5,%6,%7}, {%8,%9}, {%0,%1,%2,%3};"
        : "+f"(c[0]), "+f"(c[1]), "+f"(c[2]), "+f"(c[3])
        : "r"(a[0]), "r"(a[1]), "r"(a[2]), "r"(a[3]), "r"(b[0]), "r"(b[1]));
}

__device__ __forceinline__ uint32_t h2(float x, float y) {
    __half2 h = __halves2half2(__float2half_rn(x), __float2half_rn(y));
    return *reinterpret_cast<uint32_t*>(&h);
}

__device__ __forceinline__ uint32_t hmul2u(uint32_t a, uint32_t b) {
    uint32_t d;
    asm("mul.f16x2 %0, %1, %2;" : "=r"(d) : "r"(a), "r"(b));
    return d;
}

__global__ void __launch_bounds__(512, 1)
cmp_fp16e_kernel(const int*   __restrict__ questions,
                 const float* __restrict__ qpos,
                 const float* __restrict__ wemb,
                 const float* __restrict__ cemb,
                 const float* __restrict__ wq,
                 float*       __restrict__ out)
{
    extern __shared__ char sm[];
    __shared__ int      sq[S_LEN];
    __shared__ float    sp[S_LEN];
    __shared__ uint32_t w2s[S_LEN / 2];

    const int tid  = threadIdx.x;
    const int wid  = tid >> 5;
    const int lane = tid & 31;
    const int dh   = blockIdx.x;   // d-half 0/1
    const int b    = blockIdx.y;   // batch

    if (tid < S_LEN) {
        sq[tid] = questions[b * S_LEN + tid];
        sp[tid] = qpos[b * S_LEN + tid];
    }
    if (tid < S_LEN / 2) {
        w2s[tid] = h2(wq[2 * tid], wq[2 * tid + 1]);
    }
    __syncthreads();

    const uint32_t smem_u = (uint32_t)__cvta_generic_to_shared(sm);

    const int mr = wid >> 2;       // d block (32 rows), 0..3
    const int nc = wid & 3;        // e block (32 cols), 0..3

    // ldmatrix per-lane address components ([k][256feat] tiles, 512B rows)
    const int xorv  = lane & 7;
    const int krowA = (lane & 7) | ((lane & 16) >> 1);   // A: m8-sel in bit3
    const int aCh   = (lane >> 3) & 1;
    const int krowB = (lane & 7) | (lane & 8);           // B: n8-sel in bit4
    const int bCh   = (lane >> 4) & 1;

    const uint32_t aBase = (uint32_t)krowA * 512 + (uint32_t)dh * 256 +
        (uint32_t)(((mr * 4 + aCh) ^ xorv) << 4);
    const uint32_t bBase0 = (uint32_t)krowB * 512 +
        (uint32_t)(((nc * 4 + bCh) ^ xorv) << 4);

    const int wsel = lane & 3;

    // ---- gather chunk g (32 tokens x full 256 feats) into stage g ----
    auto gather = [&](int g) {
        const uint32_t stg = smem_u + (uint32_t)g * STAGE_BYTES;
#pragma unroll
        for (int i = 0; i < 4; ++i) {
            const int t  = tid + i * 512;        // 0..2047
            const int k  = t >> 6;               // 0..31
            const int f4 = t & 63;               // 0..63 (full feat range)

            const int   s  = g * KC + k;
            const int   q  = sq[s];
            const float pp = sp[s];
            const float4 rv = *(const float4*)(wemb + (size_t)q * D_DIM + f4 * 4);
            const float4 cv = *(const float4*)(cemb + (size_t)q * D_DIM + f4 * 4);

            const uint32_t dst = stg +
                (uint32_t)k * 512 +
                (uint32_t)((((f4 >> 1) ^ (k & 7)) << 4) + (f4 & 1) * 8);

            uint2 vR = make_uint2(h2(rv.x, rv.y), h2(rv.z, rv.w));
            uint2 vI = make_uint2(h2(cv.x * pp, cv.y * pp),
                                  h2(cv.z * pp, cv.w * pp));
            asm volatile("st.shared.v2.b32 [%0], {%1,%2};"
                         :: "r"(dst + R_OFF), "r"(vR.x), "r"(vR.y));
            asm volatile("st.shared.v2.b32 [%0], {%1,%2};"
                         :: "r"(dst + I_OFF), "r"(vI.x), "r"(vI.y));
        }
    };

    float accRe[2][4][4];
    float accIm[2][4][4];

    // ---- compute one chunk into acc, B scaled by w on the fly ----
    auto compute = [&](int g, uint32_t bBase) {
        const uint32_t stg = smem_u + (uint32_t)g * STAGE_BYTES;
#pragma unroll
        for (int kg2 = 0; kg2 < 2; ++kg2) {
            const uint32_t kofs = (uint32_t)kg2 * 8192;   // 16 k-rows * 512B
            const int wbase = (g * 2 + kg2) * 8;
            const uint32_t w2lo = w2s[wbase + wsel];
            const uint32_t w2hi = w2s[wbase + 4 + wsel];

            uint32_t bR[8], bI[8];
#pragma unroll
            for (int ntp = 0; ntp < 2; ++ntp) {
                const uint32_t badj = bBase ^ (uint32_t)(ntp * 32);
                uint32_t tR[4], tI[4];
                ldmx4t(tR, stg + R_OFF + kofs + badj);
                ldmx4t(tI, stg + I_OFF + kofs + badj);
#pragma unroll
                for (int j = 0; j < 4; ++j) {
                    const uint32_t wv = (j & 1) ? w2hi : w2lo;
                    bR[4 * ntp + j] = hmul2u(tR[j], wv);
                    bI[4 * ntp + j] = hmul2u(tI[j], wv);
                }
            }

#pragma unroll
            for (int mt = 0; mt < 2; ++mt) {
                const uint32_t aadj = aBase ^ (uint32_t)(mt * 32);
                uint32_t aR[4], aI[4], aN[4];
                ldmx4t(aR, stg + R_OFF + kofs + aadj);
                ldmx4t(aI, stg + I_OFF + kofs + aadj);
#pragma unroll
                for (int j = 0; j < 4; ++j) aN[j] = aR[j] ^ 0x80008000u;

#pragma unroll
                for (int nt = 0; nt < 4; ++nt) {
                    const int bi = (nt >> 1) * 4 + (nt & 1) * 2;
                    mma16(accRe[mt][nt], aR, bR + bi);
                }
#pragma unroll
                for (int nt = 0; nt < 4; ++nt) {
                    const int bi = (nt >> 1) * 4 + (nt & 1) * 2;
                    mma16(accRe[mt][nt], aI, bI + bi);
                }
#pragma unroll
                for (int nt = 0; nt < 4; ++nt) {
                    const int bi = (nt >> 1) * 4 + (nt & 1) * 2;
                    mma16(accIm[mt][nt], aI, bR + bi);
                }
#pragma unroll
                for (int nt = 0; nt < 4; ++nt) {
                    const int bi = (nt >> 1) * 4 + (nt & 1) * 2;
                    mma16(accIm[mt][nt], aN, bI + bi);
                }
            }
        }
    };

    const int r = lane >> 2;
    const int c = lane & 3;
    float* oRe = out + (size_t)b * D_DIM * D_DIM;
    float* oIm = oRe + (size_t)B_DIM * D_DIM * D_DIM;

    auto epilogue = [&](int et) {
#pragma unroll
        for (int mt = 0; mt < 2; ++mt) {
            const int d = dh * 128 + mr * 32 + mt * 16 + r;
#pragma unroll
            for (int nt = 0; nt < 4; ++nt) {
                const int e = et * 128 + nc * 32 + nt * 8 + 2 * c;
                *(float2*)(oRe + (size_t)d * D_DIM + e) =
                    make_float2(accRe[mt][nt][0], accRe[mt][nt][1]);
                *(float2*)(oRe + (size_t)(d + 8) * D_DIM + e) =
                    make_float2(accRe[mt][nt][2], accRe[mt][nt][3]);
                *(float2*)(oIm + (size_t)d * D_DIM + e) =
                    make_float2(accIm[mt][nt][0], accIm[mt][nt][1]);
                *(float2*)(oIm + (size_t)(d + 8) * D_DIM + e) =
                    make_float2(accIm[mt][nt][2], accIm[mt][nt][3]);
            }
        }
    };

    auto clear_acc = [&]() {
#pragma unroll
        for (int i = 0; i < 2; i++)
#pragma unroll
            for (int j = 0; j < 4; j++)
#pragma unroll
                for (int q = 0; q < 4; q++) { accRe[i][j][q] = 0.f; accIm[i][j][q] = 0.f; }
    };

    // ================= pipelined et=0 pass (gathers all 4 stages) =========
    clear_acc();
    gather(0);
    __syncthreads();
    gather(1); compute(0, bBase0);
    __syncthreads();
    gather(2); compute(1, bBase0);
    __syncthreads();
    gather(3); compute(2, bBase0);
    __syncthreads();
    compute(3, bBase0);
    epilogue(0);

    // ================= et=1 pass: pure MMA from resident smem ==============
    clear_acc();
    const uint32_t bBase1 = bBase0 + 256;
    compute(0, bBase1);
    compute(1, bBase1);
    compute(2, bBase1);
    compute(3, bBase1);
    epilogue(1);
}

extern "C" void kernel_launch(void* const* d_in, const int* in_sizes, int n_in,
                              void* d_out, int out_size) {
    const int*   questions = (const int*)d_in[0];
    const float* qpos      = (const float*)d_in[1];
    const float* wemb      = (const float*)d_in[2];
    const float* cemb      = (const float*)d_in[3];
    const float* wq        = (const float*)d_in[4];
    float*       out       = (float*)d_out;

    cudaFuncSetAttribute(cmp_fp16e_kernel,
                         cudaFuncAttributeMaxDynamicSharedMemorySize, SMEM_BYTES);

    dim3 grid(2 /*d-half*/, B_DIM /*batch*/);
    cmp_fp16e_kernel<<<grid, 512, SMEM_BYTES>>>(questions, qpos, wemb, cemb,
                                                wq, out);
}

// round 14
// speedup vs baseline: 1.3007x; 1.3007x over previous
#include <cuda_runtime.h>
#include <cuda_fp16.h>
#include <cstdint>

// CMPModel density matrix via fp16 mma.sync m16n8k16 (f32 accum), sm_103.
// V=50000, D=256, S=128, B=64.
//
// R[k,d]=word_emb[q[k],d], I[k,d]=cmp_emb[q[k],d]*pos[k]
//   real[d,e] = sum_k w[k]( R[k,d]R[k,e] + I[k,d]I[k,e] )
//   imag[d,e] = sum_k w[k]( I[k,d]R[k,e] - R[k,d]I[k,e] )
//
// CTA = (e-half, d-half, batch), 256 CTAs (L2-optimal quadrant shape).
// ALL tiles stored UNSCALED (R, pos*I as fp16); w applied to B fragments
// in compute via mul.f16x2 (w-pair table) -> gather chains are short:
// LDG -> 4 mul -> cvt.rn.f16x2 (1 instr) -> STS.  Diagonal CTAs (dt==et)
// load only the A tiles and read B fragments from them (half the LDGs).
// Fragments via ldmatrix.x4.trans ([k][128feat] tiles, 256B rows,
// ^(k&7) swizzle).  Imag minus sign: negate aR fragment (XOR 0x80008000).

#define D_DIM 256
#define S_LEN 128
#define B_DIM 64
#define KC    32

#define TILE_BYTES  8192                    // 32 k x 128 feat x 2B
#define STAGE_BYTES 32768
#define SMEM_BYTES  (2 * STAGE_BYTES)       // 64KB

#define AR_OFF 0
#define AI_OFF 8192
#define BR_OFF 16384
#define BI_OFF 24576

__device__ __forceinline__ void ldmx4t(uint32_t* r, uint32_t addr) {
    asm("ldmatrix.sync.aligned.m8n8.x4.trans.shared.b16 {%0,%1,%2,%3}, [%4];"
        : "=r"(r[0]), "=r"(r[1]), "=r"(r[2]), "=r"(r[3]) : "r"(addr));
}

__device__ __forceinline__ void mma16(float* c, const uint32_t* a,
                                      const uint32_t* b) {
    asm("mma.sync.aligned.m16n8k16.row.col.f32.f16.f16.f32 "
        "{%0,%1,%2,%3}, {%4,%5,%6,%7}, {%8,%9}, {%0,%1,%2,%3};"
        : "+f"(c[0]), "+f"(c[1]), "+f"(c[2]), "+f"(c[3])
        : "r"(a[0]), "r"(a[1]), "r"(a[2]), "r"(a[3]), "r"(b[0]), "r"(b[1]));
}

// pack two f32 into f16x2 with ONE cvt instruction (lo=x, hi=y)
__device__ __forceinline__ uint32_t h2(float x, float y) {
    uint32_t r;
    asm("cvt.rn.f16x2.f32 %0, %1, %2;" : "=r"(r) : "f"(y), "f"(x));
    return r;
}

__device__ __forceinline__ uint32_t hmul2u(uint32_t a, uint32_t b) {
    uint32_t d;
    asm("mul.f16x2 %0, %1, %2;" : "=r"(d) : "r"(a), "r"(b));
    return d;
}

__global__ void __launch_bounds__(512, 1)
cmp_fp16f_kernel(const int*   __restrict__ questions,
                 const float* __restrict__ qpos,
                 const float* __restrict__ wemb,
                 const float* __restrict__ cemb,
                 const float* __restrict__ wq,
                 float*       __restrict__ out)
{
    extern __shared__ char sm[];
    __shared__ int      sq[S_LEN];
    __shared__ float    sp[S_LEN];
    __shared__ uint32_t w2s[S_LEN / 2];

    const int tid  = threadIdx.x;
    const int wid  = tid >> 5;
    const int lane = tid & 31;
    const int et   = blockIdx.x;
    const int dt   = blockIdx.y;
    const int b    = blockIdx.z;
    const bool diag = (et == dt);

    if (tid < S_LEN) {
        sq[tid] = questions[b * S_LEN + tid];
        sp[tid] = qpos[b * S_LEN + tid];
    }
    if (tid < S_LEN / 2) {
        w2s[tid] = h2(wq[2 * tid], wq[2 * tid + 1]);
    }
    __syncthreads();

    const uint32_t smem_u = (uint32_t)__cvta_generic_to_shared(sm);

    const int mr = wid >> 2;       // d block (32 rows), 0..3
    const int nc = wid & 3;        // e block (32 cols), 0..3

    float accRe[2][4][4];
    float accIm[2][4][4];
#pragma unroll
    for (int i = 0; i < 2; i++)
#pragma unroll
        for (int j = 0; j < 4; j++)
#pragma unroll
            for (int q = 0; q < 4; q++) { accRe[i][j][q] = 0.f; accIm[i][j][q] = 0.f; }

    // ldmatrix per-lane address components
    const int xorv  = lane & 7;
    const int krowA = (lane & 7) | ((lane & 16) >> 1);   // A: m8-sel in bit3
    const int aCh   = (lane >> 3) & 1;
    const int krowB = (lane & 7) | (lane & 8);           // B: n8-sel in bit4
    const int bCh   = (lane >> 4) & 1;

    const uint32_t aBase = (uint32_t)krowA * 256 +
        (uint32_t)(((mr * 4 + aCh) ^ xorv) * 16);
    const uint32_t bBase = (uint32_t)krowB * 256 +
        (uint32_t)(((nc * 4 + bCh) ^ xorv) * 16);

    const int wsel = lane & 3;

    // B fragments come from the A tiles on diagonal CTAs (same feat half)
    const uint32_t bROff = diag ? AR_OFF : BR_OFF;
    const uint32_t bIOff = diag ? AI_OFF : BI_OFF;

    // ---- gather chunk g into stage buffer (unscaled R, pos*I) ----
    auto gather = [&](int g) {
        const uint32_t stg = smem_u + (uint32_t)(g & 1) * STAGE_BYTES;
        const int niter = diag ? 2 : 4;      // diag: A tiles only
#pragma unroll
        for (int i = 0; i < 4; ++i) {
            if (i >= niter) break;
            const int t    = tid + i * 512;
            const int half = t >> 10;            // 0: A (dt-half), 1: B (et-half)
            const int k    = (t >> 5) & 31;
            const int f4   = t & 31;
            const int fofs = (half ? et : dt) * 128 + f4 * 4;

            const int   s  = g * KC + k;
            const int   q  = sq[s];
            const float pp = sp[s];
            const float4 rv = *(const float4*)(wemb + (size_t)q * D_DIM + fofs);
            const float4 cv = *(const float4*)(cemb + (size_t)q * D_DIM + fofs);

            const uint32_t dst = stg + (half ? BR_OFF : AR_OFF) +
                (uint32_t)k * 256 +
                (uint32_t)(((f4 >> 1) ^ (k & 7)) * 16 + (f4 & 1) * 8);

            uint2 vR = make_uint2(h2(rv.x, rv.y), h2(rv.z, rv.w));
            uint2 vI = make_uint2(h2(cv.x * pp, cv.y * pp),
                                  h2(cv.z * pp, cv.w * pp));
            asm volatile("st.shared.v2.b32 [%0], {%1,%2};"
                         :: "r"(dst), "r"(vR.x), "r"(vR.y));
            asm volatile("st.shared.v2.b32 [%0], {%1,%2};"
                         :: "r"(dst + 8192), "r"(vI.x), "r"(vI.y));
        }
    };

    gather(0);
    __syncthreads();

    for (int g = 0; g < 4; ++g) {
        const uint32_t stg = smem_u + (uint32_t)(g & 1) * STAGE_BYTES;
        if (g < 3) gather(g + 1);   // fills other stage; overlaps compute

#pragma unroll
        for (int kg = 0; kg < 2; ++kg) {
            const uint32_t kofs = (uint32_t)kg * 4096;
            const int wbase = (g * 2 + kg) * 8;
            const uint32_t w2lo = w2s[wbase + wsel];
            const uint32_t w2hi = w2s[wbase + 4 + wsel];

            // ---- B fragments: unscaled loads, then w via mul.f16x2 ----
            uint32_t bR[8], bI[8];
#pragma unroll
            for (int ntp = 0; ntp < 2; ++ntp) {
                const uint32_t badj = bBase ^ (uint32_t)(ntp * 32);
                uint32_t tR[4], tI[4];
                ldmx4t(tR, stg + bROff + kofs + badj);
                ldmx4t(tI, stg + bIOff + kofs + badj);
#pragma unroll
                for (int j = 0; j < 4; ++j) {
                    const uint32_t wv = (j & 1) ? w2hi : w2lo;
                    bR[4 * ntp + j] = hmul2u(tR[j], wv);
                    bI[4 * ntp + j] = hmul2u(tI[j], wv);
                }
            }

            // ---- A fragments + MMAs (pass-major, RAW distance 4) ----
#pragma unroll
            for (int mt = 0; mt < 2; ++mt) {
                const uint32_t aadj = aBase ^ (uint32_t)(mt * 32);
                uint32_t aR[4], aI[4], aN[4];
                ldmx4t(aR, stg + AR_OFF + kofs + aadj);
                ldmx4t(aI, stg + AI_OFF + kofs + aadj);
#pragma unroll
                for (int j = 0; j < 4; ++j) aN[j] = aR[j] ^ 0x80008000u;

#pragma unroll
                for (int nt = 0; nt < 4; ++nt) {
                    const int bi = (nt >> 1) * 4 + (nt & 1) * 2;
                    mma16(accRe[mt][nt], aR, bR + bi);
                }
#pragma unroll
                for (int nt = 0; nt < 4; ++nt) {
                    const int bi = (nt >> 1) * 4 + (nt & 1) * 2;
                    mma16(accRe[mt][nt], aI, bI + bi);
                }
#pragma unroll
                for (int nt = 0; nt < 4; ++nt) {
                    const int bi = (nt >> 1) * 4 + (nt & 1) * 2;
                    mma16(accIm[mt][nt], aI, bR + bi);
                }
#pragma unroll
                for (int nt = 0; nt < 4; ++nt) {
                    const int bi = (nt >> 1) * 4 + (nt & 1) * 2;
                    mma16(accIm[mt][nt], aN, bI + bi);
                }
            }
        }
        __syncthreads();
    }

    // ---- epilogue ----
    const int r = lane >> 2;
    const int c = lane & 3;
    float* oRe = out + (size_t)b * D_DIM * D_DIM;
    float* oIm = oRe + (size_t)B_DIM * D_DIM * D_DIM;
#pragma unroll
    for (int mt = 0; mt < 2; ++mt) {
        const int d = dt * 128 + mr * 32 + mt * 16 + r;
#pragma unroll
        for (int nt = 0; nt < 4; ++nt) {
            const int e = et * 128 + nc * 32 + nt * 8 + 2 * c;
            *(float2*)(oRe + (size_t)d * D_DIM + e) =
                make_float2(accRe[mt][nt][0], accRe[mt][nt][1]);
            *(float2*)(oRe + (size_t)(d + 8) * D_DIM + e) =
                make_float2(accRe[mt][nt][2], accRe[mt][nt][3]);
            *(float2*)(oIm + (size_t)d * D_DIM + e) =
                make_float2(accIm[mt][nt][0], accIm[mt][nt][1]);
            *(float2*)(oIm + (size_t)(d + 8) * D_DIM + e) =
                make_float2(accIm[mt][nt][2], accIm[mt][nt][3]);
        }
    }
}

extern "C" void kernel_launch(void* const* d_in, const int* in_sizes, int n_in,
                              void* d_out, int out_size) {
    const int*   questions = (const int*)d_in[0];
    const float* qpos      = (const float*)d_in[1];
    const float* wemb      = (const float*)d_in[2];
    const float* cemb      = (const float*)d_in[3];
    const float* wq        = (const float*)d_in[4];
    float*       out       = (float*)d_out;

    cudaFuncSetAttribute(cmp_fp16f_kernel,
                         cudaFuncAttributeMaxDynamicSharedMemorySize, SMEM_BYTES);

    dim3 grid(2 /*e-half*/, 2 /*d-half*/, B_DIM);
    cmp_fp16f_kernel<<<grid, 512, SMEM_BYTES>>>(questions, qpos, wemb, cemb,
                                                wq, out);
}